// round 6
// baseline (speedup 1.0000x reference)
#include <cuda_runtime.h>

#define B_   128
#define R_   1152
#define J_   10
#define D_   16
#define JD_  160
#define CIN_ 8
#define GRID 144
#define RC   8      // routes per block (144*8 = 1152)
#define NT   640    // (jdp in [0,80)) x (bt in [0,8))

typedef unsigned long long ull;

// ---- global scratch ----
__device__ ull g_part2[(size_t)GRID * 64 * JD_];  // [blk][bp][jd], f32x2 over batch pair
__device__ ull g_v2[64 * JD_];                    // [bp][jd]
__device__ unsigned g_cnt = 0;
__device__ volatile unsigned g_gen = 0;

// ---- smem layout (float offsets) ----
#define SW_OFF 0                      // W transposed: (r*8+c)*160 + jd ; 10240 f
#define SX_OFF 10240                  // x packed:     (r*8+c)*132 + b  ; 8448 f (pad 4)
#define SV_OFF (10240 + 8448)         // v f32x2:  ull[bp*160+jd]       ; 20480 f
#define SC_OFF (SV_OFF + 20480)       // c[r*16+j]                      ; 128 f
#define SB_OFF (SC_OFF + 128)         // b_ij[r*16+j]                   ; 128 f
#define SD_OFF (SB_OFF + 128)         // delta partials [r*80+j*8+bt]   ; 640 f
#define SMEM_FLOATS (SD_OFF + 640)
#define SMEM_BYTES  (SMEM_FLOATS * 4) // 160,256 B

// ---- packed f32x2 helpers ----
__device__ __forceinline__ ull pack2(float lo, float hi) {
    ull r;
    asm("mov.b64 %0, {%1, %2};" : "=l"(r)
        : "r"(__float_as_uint(lo)), "r"(__float_as_uint(hi)));
    return r;
}
__device__ __forceinline__ float2 unpack2(ull v) {
    unsigned lo, hi;
    asm("mov.b64 {%0, %1}, %2;" : "=r"(lo), "=r"(hi) : "l"(v));
    return make_float2(__uint_as_float(lo), __uint_as_float(hi));
}
__device__ __forceinline__ void ffma2(ull& d, ull a, ull b) {
    asm("fma.rn.f32x2 %0, %1, %2, %0;" : "+l"(d) : "l"(a), "l"(b));
}
__device__ __forceinline__ ull add2(ull a, ull b) {
    ull r; asm("add.rn.f32x2 %0, %1, %2;" : "=l"(r) : "l"(a), "l"(b)); return r;
}
__device__ __forceinline__ ull mul2(ull a, ull b) {
    ull r; asm("mul.rn.f32x2 %0, %1, %2;" : "=l"(r) : "l"(a), "l"(b)); return r;
}

// ---- one-wave grid barrier ----
__device__ __forceinline__ void grid_sync(int t) {
    __syncthreads();
    if (t == 0) {
        __threadfence();
        unsigned gen = g_gen;
        if (atomicAdd(&g_cnt, 1u) == GRID - 1) {
            atomicExch(&g_cnt, 0u);
            __threadfence();
            g_gen = gen + 1;
        } else {
            while (g_gen == gen) { __nanosleep(64); }
        }
        __threadfence();
    }
    __syncthreads();
}

// ---------------------------------------------------------------------------
// s-phase: acc[ji][bpl] (f32x2 over batch pair) += coef(r,j) * u_hat
// ---------------------------------------------------------------------------
__device__ __forceinline__ void s_phase(float* sm, int jdp, int bt, int j,
                                        int blk, int uniform) {
    const int jd0 = 2 * jdp;
    const float* sW = sm + SW_OFF;
    const ull*   sX = (const ull*)(sm + SX_OFF);
    const float* sC = sm + SC_OFF;

    ull acc[2][8];
#pragma unroll
    for (int a = 0; a < 2; a++)
#pragma unroll
        for (int b = 0; b < 8; b++) acc[a][b] = 0ull;

#pragma unroll
    for (int r = 0; r < RC; r++) {
        float coef = uniform ? 0.1f : sC[r * 16 + j];
#pragma unroll
        for (int c = 0; c < CIN_; c++) {
            float2 wv = *(const float2*)(sW + (r * 8 + c) * JD_ + jd0);
            ull w0 = pack2(wv.x * coef, wv.x * coef);
            ull w1 = pack2(wv.y * coef, wv.y * coef);
            const ulonglong2* xq =
                (const ulonglong2*)(sX + (r * 8 + c) * 66 + bt * 8);
            ulonglong2 q0 = xq[0], q1 = xq[1], q2 = xq[2], q3 = xq[3];
            ffma2(acc[0][0], w0, q0.x); ffma2(acc[1][0], w1, q0.x);
            ffma2(acc[0][1], w0, q0.y); ffma2(acc[1][1], w1, q0.y);
            ffma2(acc[0][2], w0, q1.x); ffma2(acc[1][2], w1, q1.x);
            ffma2(acc[0][3], w0, q1.y); ffma2(acc[1][3], w1, q1.y);
            ffma2(acc[0][4], w0, q2.x); ffma2(acc[1][4], w1, q2.x);
            ffma2(acc[0][5], w0, q2.y); ffma2(acc[1][5], w1, q2.y);
            ffma2(acc[0][6], w0, q3.x); ffma2(acc[1][6], w1, q3.x);
            ffma2(acc[0][7], w0, q3.y); ffma2(acc[1][7], w1, q3.y);
        }
    }

    ull* gp = g_part2 + (size_t)blk * (64 * JD_);
#pragma unroll
    for (int bpl = 0; bpl < 8; bpl++) {
        // [bp][jd0..jd0+1] -> contiguous 16B, coalesced STG.128 across jdp lanes
        *(ulonglong2*)(gp + (bt * 8 + bpl) * JD_ + jd0) =
            make_ulonglong2(acc[0][bpl], acc[1][bpl]);
    }
}

// ---------------------------------------------------------------------------
// reduce + squash (blocks 0..15; 16*640 threads x 1 ull = 20480 outputs)
// ---------------------------------------------------------------------------
__device__ __forceinline__ void reduce_squash(int blk, int t, float* out,
                                              int final_out) {
    if (blk >= 16) return;
    int u = blk * NT + t;               // u = bp*160 + jd
    ull s2 = 0ull;
    const ull* p = g_part2 + u;
#pragma unroll 8
    for (int k = 0; k < GRID; k++)
        s2 = add2(s2, __ldcg(p + (size_t)k * (64 * JD_)));

    ull sq2 = mul2(s2, s2);
#pragma unroll
    for (int o = 8; o; o >>= 1)
        sq2 = add2(sq2, __shfl_xor_sync(0xffffffffu, sq2, o, 16));

    float2 s = unpack2(s2), q = unpack2(sq2);
    float sc0 = sqrtf(q.x) / (1.f + q.x);
    float sc1 = sqrtf(q.y) / (1.f + q.y);
    if (final_out) {
        int bp = u / JD_, jd = u % JD_;
        out[(2 * bp) * JD_ + jd]     = s.x * sc0;
        out[(2 * bp + 1) * JD_ + jd] = s.y * sc1;
    } else {
        g_v2[u] = pack2(s.x * sc0, s.y * sc1);
    }
}

// ---------------------------------------------------------------------------
// delta-phase: delta[r,j] = mean_b sum_d u_hat*v; b_ij += delta; c = softmax_j
// ---------------------------------------------------------------------------
__device__ __forceinline__ void delta_phase(float* sm, int jdp, int bt, int j,
                                            int first, int t) {
    // stage v (f32x2) into smem
    ull* sV = (ull*)(sm + SV_OFF);
    for (int i = t; i < 64 * JD_; i += NT) sV[i] = __ldcg(g_v2 + i);
    __syncthreads();

    const int jd0 = 2 * jdp;
    const float* sW = sm + SW_OFF;
    const ull*   sX = (const ull*)(sm + SX_OFF);
    float* sC = sm + SC_OFF;
    float* sB = sm + SB_OFF;
    float* sD = sm + SD_OFF;

#pragma unroll
    for (int r = 0; r < RC; r++) {
        ull u2[2][8];
#pragma unroll
        for (int a = 0; a < 2; a++)
#pragma unroll
            for (int b = 0; b < 8; b++) u2[a][b] = 0ull;

#pragma unroll
        for (int c = 0; c < CIN_; c++) {
            float2 wv = *(const float2*)(sW + (r * 8 + c) * JD_ + jd0);
            ull w0 = pack2(wv.x, wv.x);
            ull w1 = pack2(wv.y, wv.y);
            const ulonglong2* xq =
                (const ulonglong2*)(sX + (r * 8 + c) * 66 + bt * 8);
            ulonglong2 q0 = xq[0], q1 = xq[1], q2 = xq[2], q3 = xq[3];
            ffma2(u2[0][0], w0, q0.x); ffma2(u2[1][0], w1, q0.x);
            ffma2(u2[0][1], w0, q0.y); ffma2(u2[1][1], w1, q0.y);
            ffma2(u2[0][2], w0, q1.x); ffma2(u2[1][2], w1, q1.x);
            ffma2(u2[0][3], w0, q1.y); ffma2(u2[1][3], w1, q1.y);
            ffma2(u2[0][4], w0, q2.x); ffma2(u2[1][4], w1, q2.x);
            ffma2(u2[0][5], w0, q2.y); ffma2(u2[1][5], w1, q2.y);
            ffma2(u2[0][6], w0, q3.x); ffma2(u2[1][6], w1, q3.x);
            ffma2(u2[0][7], w0, q3.y); ffma2(u2[1][7], w1, q3.y);
        }

        ull da = 0ull, db = 0ull;  // two chains
#pragma unroll
        for (int bpl = 0; bpl < 8; bpl++) {
            ull v0 = sV[(bt * 8 + bpl) * JD_ + jd0];
            ull v1 = sV[(bt * 8 + bpl) * JD_ + jd0 + 1];
            ffma2(da, u2[0][bpl], v0);
            ffma2(db, u2[1][bpl], v1);
        }
        float2 a = unpack2(da), b2 = unpack2(db);
        float dr = a.x + a.y + b2.x + b2.y;   // 2 d-cols x 2 b
#pragma unroll
        for (int o = 4; o; o >>= 1)
            dr += __shfl_xor_sync(0xffffffffu, dr, o, 8);   // over 16 d of j
        if ((jdp & 7) == 0) sD[r * 80 + j * 8 + bt] = dr;
    }
    __syncthreads();

    if (t < 80) {   // one thread per (r,j)
        int r = t / 10, q = t % 10;
        float val = 0.f;
#pragma unroll
        for (int k = 0; k < 8; k++) val += sD[r * 80 + q * 8 + k];
        val *= (1.f / (float)B_);
        if (!first) val += sB[r * 16 + q];
        sB[r * 16 + q] = val;
    }
    __syncthreads();
    if (t < 80) {
        int r = t / 10, q = t % 10;
        float m = -1e30f;
#pragma unroll
        for (int k = 0; k < J_; k++) m = fmaxf(m, sB[r * 16 + k]);
        float den = 0.f;
#pragma unroll
        for (int k = 0; k < J_; k++) den += expf(sB[r * 16 + k] - m);
        sC[r * 16 + q] = expf(sB[r * 16 + q] - m) / den;
    }
    __syncthreads();
}

// ---------------------------------------------------------------------------
__global__ void __launch_bounds__(NT, 1)
caps_kernel(const float* __restrict__ x, const float* __restrict__ W,
            float* __restrict__ out) {
    extern __shared__ float sm[];
    int t   = threadIdx.x;
    int blk = blockIdx.x;
    int jdp = t % 80;
    int bt  = t / 80;
    int j   = jdp >> 3;
    int r0  = blk * RC;

    // Load W chunk, transposing [r][jd][c] -> [r][c][jd]
    const float4* Wg4 = (const float4*)(W + (size_t)r0 * (JD_ * CIN_));
    for (int i = t; i < RC * JD_ * 2; i += NT) {   // 2560 float4
        int r = i / 320, rem = i % 320, jd = rem >> 1, h = rem & 1;
        float4 f = Wg4[i];
        float* dst = sm + SW_OFF + (r * 8 + 4 * h) * JD_ + jd;
        dst[0]       = f.x;
        dst[JD_]     = f.y;
        dst[2 * JD_] = f.z;
        dst[3 * JD_] = f.w;
    }
    // Load x chunk -> [r][c] rows of 128 b (padded row stride 132)
    for (int i = t; i < RC * B_ * CIN_; i += NT) {
        int b = i >> 6, rc = i & 63;
        sm[SX_OFF + rc * 132 + b] = x[(size_t)b * (R_ * CIN_) + r0 * CIN_ + rc];
    }
    __syncthreads();

    // iter 1 (uniform c = 0.1)
    s_phase(sm, jdp, bt, j, blk, 1);
    grid_sync(t);
    reduce_squash(blk, t, out, 0);            // v1 -> g_v2
    grid_sync(t);

    // iter 2
    delta_phase(sm, jdp, bt, j, 1, t);        // b1, c2
    s_phase(sm, jdp, bt, j, blk, 0);          // s2
    grid_sync(t);
    reduce_squash(blk, t, out, 0);            // v2 -> g_v2
    grid_sync(t);

    // iter 3
    delta_phase(sm, jdp, bt, j, 0, t);        // b2, c3
    s_phase(sm, jdp, bt, j, blk, 0);          // s3
    grid_sync(t);
    reduce_squash(blk, t, out, 1);            // v3 -> out [B,10,16,1]
}

// ---------------------------------------------------------------------------
extern "C" void kernel_launch(void* const* d_in, const int* in_sizes, int n_in,
                              void* d_out, int out_size) {
    const float* x = (const float*)d_in[0];
    const float* W = (const float*)d_in[1];
    if (n_in >= 2 && in_sizes[0] == R_ * J_ * D_ * CIN_) {  // inputs swapped
        x = (const float*)d_in[1];
        W = (const float*)d_in[0];
    }
    cudaFuncSetAttribute(caps_kernel,
                         cudaFuncAttributeMaxDynamicSharedMemorySize, SMEM_BYTES);
    caps_kernel<<<GRID, NT, SMEM_BYTES>>>(x, W, (float*)d_out);
}

// round 7
// speedup vs baseline: 1.1329x; 1.1329x over previous
#include <cuda_runtime.h>
#include <cuda_fp16.h>

#define B_   128
#define R_   1152
#define J_   10
#define D_   16
#define JD_  160
#define CIN_ 8
#define GRID 144
#define RC   8      // routes per block
#define NT   320    // 10 warps; warp tile = 32 jd x 64 b

// ---- global scratch (device globals; no allocation allowed) ----
__device__ float g_part[(size_t)GRID * JD_ * B_];  // [blk][jd][b], 11.8MB (L2-resident)
__device__ float g_s[JD_ * B_];
__device__ unsigned short g_vh[JD_ * B_];          // v as fp16 [jd][b]
__device__ unsigned g_cnt = 0;
__device__ volatile unsigned g_gen = 0;

// ---- smem layout (float offsets) ----
// W2: [160][144]  packed per (jd,r): 8 k-slots of (k hi, k lo, k+4 hi, k+4 lo)
// X2: [128][144]  same packing, rows are b
// SVH: half2 v  as uint [160][68]
#define SW2 0
#define SX2 (160 * 144)
#define SVH (SX2 + 128 * 144)
#define SBJ (SVH + 160 * 68)      // b_ij[8][10]
#define SDD (SBJ + 80)            // delta partials [10][2]
#define SCC (SDD + 20)            // c_cur[10]
#define SMF (SCC + 16)
#define SMEM_BYTES (SMF * 4)      // ~209.9 KB

// ---- tf32 split: v = hi + lo, both tf32 ----
__device__ __forceinline__ void tf32_split(float v, unsigned& h, unsigned& l) {
    asm("cvt.rna.tf32.f32 %0, %1;" : "=r"(h) : "f"(v));
    float r = v - __uint_as_float(h);
    asm("cvt.rna.tf32.f32 %0, %1;" : "=r"(l) : "f"(r));
}

// ---- m16n8k8 tf32 mma, D += A*B ----
__device__ __forceinline__ void mma8(float* c, unsigned a0, unsigned a1,
                                     unsigned a2, unsigned a3,
                                     unsigned b0, unsigned b1) {
    asm volatile(
        "mma.sync.aligned.m16n8k8.row.col.f32.tf32.tf32.f32 "
        "{%0,%1,%2,%3}, {%4,%5,%6,%7}, {%8,%9}, {%0,%1,%2,%3};"
        : "+f"(c[0]), "+f"(c[1]), "+f"(c[2]), "+f"(c[3])
        : "r"(a0), "r"(a1), "r"(a2), "r"(a3), "r"(b0), "r"(b1));
}

// ---- one-wave grid barrier ----
__device__ __forceinline__ void grid_sync(int t) {
    __syncthreads();
    if (t == 0) {
        __threadfence();
        unsigned gen = g_gen;
        if (atomicAdd(&g_cnt, 1u) == GRID - 1) {
            atomicExch(&g_cnt, 0u);
            __threadfence();
            g_gen = gen + 1;
        } else {
            while (g_gen == gen) { __nanosleep(64); }
        }
        __threadfence();
    }
    __syncthreads();
}

// ---------------------------------------------------------------------------
// U-pass. WD=0: s = 0.1 * sum_r U_r (P1). WD=1: per r: U_r -> delta(v) ->
// softmax -> s += c*U_r. Ends by storing s partials to g_part[blk].
// ---------------------------------------------------------------------------
template <int WD>
__device__ __forceinline__ void u_pass(float* sm, int t, int blk) {
    int lane = t & 31, wid = t >> 5;
    int gid = lane >> 2, tig = lane & 3;
    int mtb = (wid % 5) * 2;          // j pair base
    int jdb = mtb * 16;               // jd base (32 rows)
    int bg  = wid / 5;                // b-group 0/1
    int bb  = bg * 64;                // b base (64 cols)

    float sacc[2][8][4];
#pragma unroll
    for (int m = 0; m < 2; m++)
#pragma unroll
        for (int n = 0; n < 8; n++)
#pragma unroll
            for (int k = 0; k < 4; k++) sacc[m][n][k] = 0.f;

    if (WD) {  // stage v (fp16) into smem
        const unsigned* gv = (const unsigned*)g_vh;
        unsigned* sv = (unsigned*)(sm + SVH);
        for (int i = t; i < 160 * 64; i += NT)
            sv[(i >> 6) * 68 + (i & 63)] = __ldcg(gv + i);
        __syncthreads();
    }

    for (int r = 0; r < RC; r++) {
        float uf[2][8][4];
        if (WD) {
#pragma unroll
            for (int m = 0; m < 2; m++)
#pragma unroll
                for (int n = 0; n < 8; n++)
#pragma unroll
                    for (int k = 0; k < 4; k++) uf[m][n][k] = 0.f;
        }

        // A fragments (W2): 2 LDS.128 per mt -> hi/lo for a0..a3
        uint4 qa[2][2];
#pragma unroll
        for (int m = 0; m < 2; m++) {
            int jd0 = jdb + m * 16 + gid;
            qa[m][0] = *(const uint4*)(sm + SW2 + jd0 * 144 + r * 16 + tig * 4);
            qa[m][1] = *(const uint4*)(sm + SW2 + (jd0 + 8) * 144 + r * 16 + tig * 4);
        }
#pragma unroll
        for (int n = 0; n < 8; n++) {
            int b = bb + n * 8 + gid;
            uint4 qb = *(const uint4*)(sm + SX2 + b * 144 + r * 16 + tig * 4);
#pragma unroll
            for (int m = 0; m < 2; m++) {
                float* acc = WD ? uf[m][n] : sacc[m][n];
                mma8(acc, qa[m][0].x, qa[m][1].x, qa[m][0].z, qa[m][1].z, qb.x, qb.z);
                mma8(acc, qa[m][0].y, qa[m][1].y, qa[m][0].w, qa[m][1].w, qb.x, qb.z);
                mma8(acc, qa[m][0].x, qa[m][1].x, qa[m][0].z, qa[m][1].z, qb.y, qb.w);
            }
        }

        if (WD) {
            // delta dot with v (fragment coords: jd = jdb+m16+gid(+8), b = bb+n8+2tig(+1))
            const unsigned* sv = (const unsigned*)(sm + SVH);
            float dj[2];
#pragma unroll
            for (int m = 0; m < 2; m++) {
                float dd = 0.f;
                int jd0 = jdb + m * 16 + gid;
#pragma unroll
                for (int n = 0; n < 8; n++) {
                    int bu = (bb >> 1) + n * 4 + tig;
                    __half2 h0 = *(const __half2*)(sv + jd0 * 68 + bu);
                    __half2 h1 = *(const __half2*)(sv + (jd0 + 8) * 68 + bu);
                    float2 f0 = __half22float2(h0), f1 = __half22float2(h1);
                    dd += uf[m][n][0] * f0.x + uf[m][n][1] * f0.y
                        + uf[m][n][2] * f1.x + uf[m][n][3] * f1.y;
                }
                dj[m] = dd;
            }
#pragma unroll
            for (int o = 16; o; o >>= 1) {
                dj[0] += __shfl_xor_sync(0xffffffffu, dj[0], o);
                dj[1] += __shfl_xor_sync(0xffffffffu, dj[1], o);
            }
            if (lane == 0) {
                sm[SDD + (mtb + 0) * 2 + bg] = dj[0];
                sm[SDD + (mtb + 1) * 2 + bg] = dj[1];
            }
            __syncthreads();
            if (t < 10) {
                float nb[J_];
                float mx = -1e30f;
#pragma unroll
                for (int q = 0; q < J_; q++) {
                    float dv = (sm[SDD + q * 2] + sm[SDD + q * 2 + 1]) * (1.f / 128.f);
                    nb[q] = sm[SBJ + r * 10 + q] + dv;
                    mx = fmaxf(mx, nb[q]);
                }
                __syncwarp(0x3ffu);       // order reads above before write below
                sm[SBJ + r * 10 + t] = nb[t];
                float den = 0.f;
#pragma unroll
                for (int q = 0; q < J_; q++) den += expf(nb[q] - mx);
                sm[SCC + t] = expf(nb[t] - mx) / den;
            }
            __syncthreads();
            float c0 = sm[SCC + mtb], c1 = sm[SCC + mtb + 1];
#pragma unroll
            for (int n = 0; n < 8; n++)
#pragma unroll
                for (int k = 0; k < 4; k++) {
                    sacc[0][n][k] += c0 * uf[0][n][k];
                    sacc[1][n][k] += c1 * uf[1][n][k];
                }
        }
    }

    // store partials [blk][jd][b] (float2, sector-coalesced)
    const float scale = WD ? 1.f : 0.1f;
    float* gp = g_part + (size_t)blk * (JD_ * B_);
#pragma unroll
    for (int m = 0; m < 2; m++) {
        int jd0 = jdb + m * 16 + gid;
#pragma unroll
        for (int n = 0; n < 8; n++) {
            int b = bb + n * 8 + tig * 2;
            *(float2*)(gp + jd0 * 128 + b) =
                make_float2(sacc[m][n][0] * scale, sacc[m][n][1] * scale);
            *(float2*)(gp + (jd0 + 8) * 128 + b) =
                make_float2(sacc[m][n][2] * scale, sacc[m][n][3] * scale);
        }
    }
}

// ---------------------------------------------------------------------------
__device__ __forceinline__ void reduce_phase(int blk, int t) {
    if (blk >= 64) return;
    int e = blk * NT + t;
    float s = 0.f;
#pragma unroll 8
    for (int k = 0; k < GRID; k++)
        s += __ldcg(g_part + (size_t)k * (JD_ * B_) + e);
    g_s[e] = s;
}

__device__ __forceinline__ void squash_phase(int blk, int t, float* out, int fin) {
    if (blk >= 64) return;
    int id = blk * NT + t;
    int d = id & 15, b = (id >> 4) & 127, j = id >> 11;
    float s = __ldcg(&g_s[(j * 16 + d) * 128 + b]);
    float sq = s * s;
#pragma unroll
    for (int o = 8; o; o >>= 1) sq += __shfl_xor_sync(0xffffffffu, sq, o, 16);
    float v = s * (sqrtf(sq) / (1.f + sq));
    if (fin) out[b * 160 + j * 16 + d] = v;
    else     g_vh[(j * 16 + d) * 128 + b] = __half_as_ushort(__float2half(v));
}

// ---------------------------------------------------------------------------
__global__ void __launch_bounds__(NT, 1)
caps_kernel(const float* __restrict__ x, const float* __restrict__ W,
            float* __restrict__ out) {
    extern __shared__ float sm[];
    int t = threadIdx.x, blk = blockIdx.x;
    int r0 = blk * RC;

    // ---- load + tf32-split W chunk into W2[jd][144] ----
    const float* Wg = W + (size_t)r0 * 1280;
    for (int i = t; i < RC * 1280; i += NT) {
        int r = i / 1280, rem = i % 1280, jd = rem >> 3, c = rem & 7;
        unsigned h, l;
        tf32_split(Wg[i], h, l);
        int o = jd * 144 + r * 16 + (c & 3) * 4 + (c >> 2) * 2;
        sm[SW2 + o]     = __uint_as_float(h);
        sm[SW2 + o + 1] = __uint_as_float(l);
    }
    // ---- load + split x chunk into X2[b][144] ----
    for (int i = t; i < B_ * 64; i += NT) {
        int b = i >> 6, rc = i & 63, r = rc >> 3, c = rc & 7;
        unsigned h, l;
        tf32_split(x[(size_t)b * (R_ * CIN_) + r0 * CIN_ + rc], h, l);
        int o = b * 144 + r * 16 + (c & 3) * 4 + (c >> 2) * 2;
        sm[SX2 + o]     = __uint_as_float(h);
        sm[SX2 + o + 1] = __uint_as_float(l);
    }
    if (t < 80) sm[SBJ + t] = 0.f;    // b_ij = 0
    __syncthreads();

    // iter 1: c uniform 0.1
    u_pass<0>(sm, t, blk);
    grid_sync(t);
    reduce_phase(blk, t);
    grid_sync(t);
    squash_phase(blk, t, out, 0);     // v1
    grid_sync(t);

    // iter 2: delta(v1) -> c2 -> s2
    u_pass<1>(sm, t, blk);
    grid_sync(t);
    reduce_phase(blk, t);
    grid_sync(t);
    squash_phase(blk, t, out, 0);     // v2
    grid_sync(t);

    // iter 3: delta(v2) -> c3 -> s3
    u_pass<1>(sm, t, blk);
    grid_sync(t);
    reduce_phase(blk, t);
    grid_sync(t);
    squash_phase(blk, t, out, 1);     // v3 -> out [B,10,16,1]
}

// ---------------------------------------------------------------------------
extern "C" void kernel_launch(void* const* d_in, const int* in_sizes, int n_in,
                              void* d_out, int out_size) {
    const float* x = (const float*)d_in[0];
    const float* W = (const float*)d_in[1];
    if (n_in >= 2 && in_sizes[0] == R_ * J_ * D_ * CIN_) {  // inputs swapped
        x = (const float*)d_in[1];
        W = (const float*)d_in[0];
    }
    cudaFuncSetAttribute(caps_kernel,
                         cudaFuncAttributeMaxDynamicSharedMemorySize, SMEM_BYTES);
    caps_kernel<<<GRID, NT, SMEM_BYTES>>>(x, W, (float*)d_out);
}

// round 8
// speedup vs baseline: 2.5207x; 2.2250x over previous
#include <cuda_runtime.h>
#include <cuda_fp16.h>

#define GRID 144
#define NT   320          // 10 warps
#define RC   8            // routes per block

typedef unsigned u32;

// ---- global scratch ----
__device__ float g_part[(size_t)GRID * 160 * 128];   // [blk][jd][b] partials, 11.8MB
__device__ unsigned short g_vh[160 * 128];           // v fp16 [jd][b]
__device__ unsigned g_cnt = 0;
__device__ volatile unsigned g_gen = 0;

// ---- smem byte offsets ----
// half buffers: W hi/lo [160][72], W' hi/lo [160][72], X hi/lo [128][72],
// XT hi/lo [64][136], V [160][136]
#define O_WH  0
#define O_WL  23040
#define O_PH  46080
#define O_PL  69120
#define O_XH  92160
#define O_XL  110592
#define O_XTH 129024
#define O_XTL 146432
#define O_V   163840
#define O_SB  207360     // float[80]  b_ij
#define O_SD  207680     // float[80]  delta
#define O_SC  208000     // float[80]  c
#define O_SR  208320     // float[256] reduce scratch
#define O_SQ  209344     // float[16]
#define SMEM_BYTES 209408

// ---- fp16 mma m16n8k16, D += A*B ----
__device__ __forceinline__ void mma16(float* c, u32 a0, u32 a1, u32 a2, u32 a3,
                                      u32 b0, u32 b1) {
    asm volatile(
        "mma.sync.aligned.m16n8k16.row.col.f32.f16.f16.f32 "
        "{%0,%1,%2,%3},{%4,%5,%6,%7},{%8,%9},{%0,%1,%2,%3};"
        : "+f"(c[0]), "+f"(c[1]), "+f"(c[2]), "+f"(c[3])
        : "r"(a0), "r"(a1), "r"(a2), "r"(a3), "r"(b0), "r"(b1));
}

__device__ __forceinline__ float2 h2f2(u32 h) {
    return __half22float2(*(const __half2*)&h);
}

// ---- one-wave grid barrier ----
__device__ __forceinline__ void grid_sync(int t) {
    __syncthreads();
    if (t == 0) {
        __threadfence();
        unsigned gen = g_gen;
        if (atomicAdd(&g_cnt, 1u) == GRID - 1) {
            atomicExch(&g_cnt, 0u);
            __threadfence();
            g_gen = gen + 1;
        } else {
            while (g_gen == gen) { __nanosleep(64); }
        }
        __threadfence();
    }
    __syncthreads();
}

// ---------------------------------------------------------------------------
// s-GEMM: partial s[jd,b] = scale * sum_rc A[jd,rc]*X[b,rc]  (A = W or c∘W)
// m=160 (warp w -> jd tile 16w), n=128 b (16 n-tiles), k=64 rc (4 k-tiles)
// 3 MMAs per (n,k): Ah*Bh + Ah*Bl + Al*Bh
// ---------------------------------------------------------------------------
__device__ __forceinline__ void s_gemm(char* smem, int t, int blk,
                                       int AH, int AL, float scale) {
    int lane = t & 31, w = t >> 5, gid = lane >> 2, tig = lane & 3;
    const u32* ah_ = (const u32*)(smem + AH);
    const u32* al_ = (const u32*)(smem + AL);
    const u32* xh_ = (const u32*)(smem + O_XH);
    const u32* xl_ = (const u32*)(smem + O_XL);
    int jr0 = (w * 16 + gid) * 36, jr1 = (w * 16 + gid + 8) * 36;

    float acc[16][4];
#pragma unroll
    for (int n = 0; n < 16; n++)
#pragma unroll
        for (int k = 0; k < 4; k++) acc[n][k] = 0.f;

#pragma unroll
    for (int kt = 0; kt < 4; kt++) {
        int ka = kt * 8 + tig;
        u32 ah0 = ah_[jr0 + ka], ah1 = ah_[jr1 + ka];
        u32 ah2 = ah_[jr0 + ka + 4], ah3 = ah_[jr1 + ka + 4];
        u32 al0 = al_[jr0 + ka], al1 = al_[jr1 + ka];
        u32 al2 = al_[jr0 + ka + 4], al3 = al_[jr1 + ka + 4];
#pragma unroll
        for (int n = 0; n < 16; n++) {
            int xb = (n * 8 + gid) * 36 + ka;
            u32 bh0 = xh_[xb], bh1 = xh_[xb + 4];
            u32 bl0 = xl_[xb], bl1 = xl_[xb + 4];
            mma16(acc[n], ah0, ah1, ah2, ah3, bh0, bh1);
            mma16(acc[n], ah0, ah1, ah2, ah3, bl0, bl1);
            mma16(acc[n], al0, al1, al2, al3, bh0, bh1);
        }
    }

    float* gp = g_part + (size_t)blk * 20480;
    int jd0 = w * 16 + gid;
#pragma unroll
    for (int n = 0; n < 16; n++) {
        int b = n * 8 + 2 * tig;
        *(float2*)(gp + jd0 * 128 + b) =
            make_float2(acc[n][0] * scale, acc[n][1] * scale);
        *(float2*)(gp + (jd0 + 8) * 128 + b) =
            make_float2(acc[n][2] * scale, acc[n][3] * scale);
    }
}

// ---------------------------------------------------------------------------
// M-GEMM + delta: M[jd,rc] = sum_b V[jd,b]*X[rc,b]; then
// delta[r=n, j=w] = sum_{d,c} W[jd,rc]*M[jd,rc]  (warp-local fragment dot)
// ---------------------------------------------------------------------------
__device__ __forceinline__ void m_delta(char* smem, int t) {
    int lane = t & 31, w = t >> 5, gid = lane >> 2, tig = lane & 3;
    const u32* v_  = (const u32*)(smem + O_V);
    const u32* bh_ = (const u32*)(smem + O_XTH);
    const u32* bl_ = (const u32*)(smem + O_XTL);
    int jr0 = (w * 16 + gid) * 68, jr1 = (w * 16 + gid + 8) * 68;

    float acc[8][4];
#pragma unroll
    for (int n = 0; n < 8; n++)
#pragma unroll
        for (int k = 0; k < 4; k++) acc[n][k] = 0.f;

#pragma unroll
    for (int kt = 0; kt < 8; kt++) {
        int ka = kt * 8 + tig;
        u32 a0 = v_[jr0 + ka], a1 = v_[jr1 + ka];
        u32 a2 = v_[jr0 + ka + 4], a3 = v_[jr1 + ka + 4];
#pragma unroll
        for (int n = 0; n < 8; n++) {
            int xb = (n * 8 + gid) * 68 + ka;
            mma16(acc[n], a0, a1, a2, a3, bh_[xb], bh_[xb + 4]);
            mma16(acc[n], a0, a1, a2, a3, bl_[xb], bl_[xb + 4]);
        }
    }

    const u32* wh_ = (const u32*)(smem + O_WH);
    const u32* wl_ = (const u32*)(smem + O_WL);
    float* sD = (float*)(smem + O_SD);
    int jw0 = (w * 16 + gid) * 36, jw1 = (w * 16 + gid + 8) * 36;
#pragma unroll
    for (int n = 0; n < 8; n++) {
        int wc = n * 4 + tig;
        float2 wa = h2f2(wh_[jw0 + wc]), wb = h2f2(wl_[jw0 + wc]);
        float2 wc0 = make_float2(wa.x + wb.x, wa.y + wb.y);
        float2 wa1 = h2f2(wh_[jw1 + wc]), wb1 = h2f2(wl_[jw1 + wc]);
        float2 wc1 = make_float2(wa1.x + wb1.x, wa1.y + wb1.y);
        float dd = acc[n][0] * wc0.x + acc[n][1] * wc0.y
                 + acc[n][2] * wc1.x + acc[n][3] * wc1.y;
#pragma unroll
        for (int o = 16; o; o >>= 1)
            dd += __shfl_xor_sync(0xffffffffu, dd, o);
        if (lane == 0) sD[n * 10 + w] = dd;
    }
}

// ---------------------------------------------------------------------------
// merged reduce + squash: blocks 0..79 each own (j, 16-b slice), all 16 d.
// ---------------------------------------------------------------------------
__device__ __forceinline__ void reduce_squash(char* smem, int blk, int t,
                                              float* out, int fin) {
    if (blk >= 80) return;
    int j = blk / 8, b0 = (blk % 8) * 16;
    float* SR = (float*)(smem + O_SR);
    float* SQ = (float*)(smem + O_SQ);
    if (t < 256) {
        int d = t >> 4, bi = t & 15;
        const float* p = g_part + (j * 16 + d) * 128 + b0 + bi;
        float s = 0.f;
#pragma unroll 8
        for (int k = 0; k < GRID; k++)
            s += __ldcg(p + (size_t)k * 20480);
        SR[t] = s;
    }
    __syncthreads();
    if (t < 16) {
        float sq = 0.f;
#pragma unroll
        for (int d = 0; d < 16; d++) { float z = SR[d * 16 + t]; sq += z * z; }
        SQ[t] = sqrtf(sq) / (1.f + sq);
    }
    __syncthreads();
    if (t < 256) {
        int d = t >> 4, bi = t & 15, b = b0 + bi;
        float v = SR[t] * SQ[bi];
        if (fin) out[b * 160 + j * 16 + d] = v;
        else g_vh[(j * 16 + d) * 128 + b] = __half_as_ushort(__float2half_rn(v));
    }
}

// ---------------------------------------------------------------------------
__device__ __forceinline__ void stage_v(char* smem, int t) {
    const u32* gv = (const u32*)g_vh;
    u32* sv = (u32*)(smem + O_V);
    for (int i = t; i < 10240; i += NT) {
        int jd = i >> 6, bu = i & 63;
        sv[jd * 68 + bu] = __ldcg(gv + i);
    }
    __syncthreads();
}

// softmax + W' rebuild (c∘W split to fp16 hi/lo)
__device__ __forceinline__ void route_update(char* smem, int t) {
    float* sB = (float*)(smem + O_SB);
    float* sD = (float*)(smem + O_SD);
    float* sC = (float*)(smem + O_SC);
    __syncthreads();                       // sD complete
    if (t < 80) sB[t] += sD[t] * (1.f / 128.f);
    __syncthreads();
    if (t < 80) {
        int r = t / 10;
        float m = -1e30f;
#pragma unroll
        for (int k = 0; k < 10; k++) m = fmaxf(m, sB[r * 10 + k]);
        float den = 0.f;
#pragma unroll
        for (int k = 0; k < 10; k++) den += expf(sB[r * 10 + k] - m);
        sC[t] = expf(sB[t] - m) / den;
    }
    __syncthreads();
    const u32* wh_ = (const u32*)(smem + O_WH);
    const u32* wl_ = (const u32*)(smem + O_WL);
    u32* ph_ = (u32*)(smem + O_PH);
    u32* pl_ = (u32*)(smem + O_PL);
    for (int i = t; i < 5120; i += NT) {   // uint pairs: jd x 32
        int jd = i >> 5, rcu = i & 31;
        float2 a = h2f2(wh_[jd * 36 + rcu]), b = h2f2(wl_[jd * 36 + rcu]);
        float c = sC[(rcu >> 2) * 10 + (jd >> 4)];
        float px = (a.x + b.x) * c, py = (a.y + b.y) * c;
        __half2 ph = __floats2half2_rn(px, py);
        float2 pf = __half22float2(ph);
        __half2 pl = __floats2half2_rn(px - pf.x, py - pf.y);
        ph_[jd * 36 + rcu] = *(u32*)&ph;
        pl_[jd * 36 + rcu] = *(u32*)&pl;
    }
    __syncthreads();
}

// ---------------------------------------------------------------------------
__global__ void __launch_bounds__(NT, 1)
caps_kernel(const float* __restrict__ x, const float* __restrict__ W,
            float* __restrict__ out) {
    extern __shared__ char smem[];
    int t = threadIdx.x, blk = blockIdx.x;

    // ---- load + fp16-split W chunk: [r][jd][c] -> halves [jd][rc] ----
    {
        __half* wh = (__half*)(smem + O_WH);
        __half* wl = (__half*)(smem + O_WL);
        const float* Wg = W + (size_t)blk * 8 * 1280;
        for (int i = t; i < 10240; i += NT) {
            int r = i / 1280, rem = i - r * 1280, jd = rem >> 3, c = rem & 7;
            float v = Wg[i];
            __half h = __float2half_rn(v);
            __half l = __float2half_rn(v - __half2float(h));
            wh[jd * 72 + r * 8 + c] = h;
            wl[jd * 72 + r * 8 + c] = l;
        }
    }
    // ---- load + split x chunk: halves [b][rc] and [rc][b] ----
    {
        __half* xh  = (__half*)(smem + O_XH);
        __half* xl  = (__half*)(smem + O_XL);
        __half* xth = (__half*)(smem + O_XTH);
        __half* xtl = (__half*)(smem + O_XTL);
        for (int i = t; i < 8192; i += NT) {
            int b = i >> 6, rc = i & 63;
            float v = x[(size_t)b * 9216 + blk * 64 + rc];
            __half h = __float2half_rn(v);
            __half l = __float2half_rn(v - __half2float(h));
            xh[b * 72 + rc] = h;   xl[b * 72 + rc] = l;
            xth[rc * 136 + b] = h; xtl[rc * 136 + b] = l;
        }
    }
    if (t < 80) ((float*)(smem + O_SB))[t] = 0.f;
    __syncthreads();

    // iter 1: c uniform 0.1 folded into store scale
    s_gemm(smem, t, blk, O_WH, O_WL, 0.1f);
    grid_sync(t);
    reduce_squash(smem, blk, t, out, 0);     // v1 -> g_vh
    grid_sync(t);

    // iter 2
    stage_v(smem, t);
    m_delta(smem, t);
    route_update(smem, t);                    // b1, c2, W'
    s_gemm(smem, t, blk, O_PH, O_PL, 1.f);
    grid_sync(t);
    reduce_squash(smem, blk, t, out, 0);     // v2 -> g_vh
    grid_sync(t);

    // iter 3
    stage_v(smem, t);
    m_delta(smem, t);
    route_update(smem, t);                    // b2, c3, W'
    s_gemm(smem, t, blk, O_PH, O_PL, 1.f);
    grid_sync(t);
    reduce_squash(smem, blk, t, out, 1);     // v3 -> out [B,10,16,1]
}

// ---------------------------------------------------------------------------
extern "C" void kernel_launch(void* const* d_in, const int* in_sizes, int n_in,
                              void* d_out, int out_size) {
    const float* x = (const float*)d_in[0];
    const float* W = (const float*)d_in[1];
    if (n_in >= 2 && in_sizes[0] == 1152 * 10 * 16 * 8) {  // inputs swapped
        x = (const float*)d_in[1];
        W = (const float*)d_in[0];
    }
    cudaFuncSetAttribute(caps_kernel,
                         cudaFuncAttributeMaxDynamicSharedMemorySize, SMEM_BYTES);
    caps_kernel<<<GRID, NT, SMEM_BYTES>>>(x, W, (float*)d_out);
}

// round 9
// speedup vs baseline: 2.6153x; 1.0375x over previous
#include <cuda_runtime.h>
#include <cuda_fp16.h>

#define GRID 144
#define NT   640          // 20 warps
#define RC   8            // routes per block

typedef unsigned u32;

// ---- global scratch ----
__device__ float g_part[(size_t)GRID * 160 * 128];   // [blk][jd][b] partials, 11.8MB
__device__ unsigned short g_vh[160 * 128];           // v fp16 [jd][b]
__device__ unsigned g_cnt = 0;
__device__ volatile unsigned g_gen = 0;

// ---- smem byte offsets ----
#define O_WH  0
#define O_WL  23040
#define O_PH  46080
#define O_PL  69120
#define O_XH  92160
#define O_XL  110592
#define O_XTH 129024
#define O_XTL 146432
#define O_V   163840
#define O_SB  207360     // float[80]  b_ij
#define O_SD  207680     // float[80]  delta
#define O_SC  208000     // float[80]  c
#define O_SR  208320     // float[256]
#define O_SQ  209344     // float[16]
#define O_SR2 209408     // float[512]
#define SMEM_BYTES 211456

// ---- fp16 mma m16n8k16, D += A*B ----
__device__ __forceinline__ void mma16(float* c, u32 a0, u32 a1, u32 a2, u32 a3,
                                      u32 b0, u32 b1) {
    asm volatile(
        "mma.sync.aligned.m16n8k16.row.col.f32.f16.f16.f32 "
        "{%0,%1,%2,%3},{%4,%5,%6,%7},{%8,%9},{%0,%1,%2,%3};"
        : "+f"(c[0]), "+f"(c[1]), "+f"(c[2]), "+f"(c[3])
        : "r"(a0), "r"(a1), "r"(a2), "r"(a3), "r"(b0), "r"(b1));
}

__device__ __forceinline__ float2 h2f2(u32 h) {
    return __half22float2(*(const __half2*)&h);
}

// ---- one-wave grid barrier ----
__device__ __forceinline__ void grid_sync(int t) {
    __syncthreads();
    if (t == 0) {
        __threadfence();
        unsigned gen = g_gen;
        if (atomicAdd(&g_cnt, 1u) == GRID - 1) {
            atomicExch(&g_cnt, 0u);
            __threadfence();
            g_gen = gen + 1;
        } else {
            while (g_gen == gen) { __nanosleep(64); }
        }
        __threadfence();
    }
    __syncthreads();
}

// ---------------------------------------------------------------------------
// s-GEMM: partial s[jd,b] = scale * sum_rc A[jd,rc]*X[b,rc]
// 20 warps: warp = (mt in [0,10), nh in {0,1}); tile 16 jd x 64 b
// ---------------------------------------------------------------------------
__device__ __forceinline__ void s_gemm(char* smem, int t, int blk,
                                       int AH, int AL, float scale) {
    int lane = t & 31, w = t >> 5, gid = lane >> 2, tig = lane & 3;
    int mt = w % 10, nh = w / 10;
    const u32* ah_ = (const u32*)(smem + AH);
    const u32* al_ = (const u32*)(smem + AL);
    const u32* xh_ = (const u32*)(smem + O_XH);
    const u32* xl_ = (const u32*)(smem + O_XL);
    int jr0 = (mt * 16 + gid) * 36, jr1 = (mt * 16 + gid + 8) * 36;

    float acc[8][4];
#pragma unroll
    for (int n = 0; n < 8; n++)
#pragma unroll
        for (int k = 0; k < 4; k++) acc[n][k] = 0.f;

#pragma unroll
    for (int kt = 0; kt < 4; kt++) {
        int ka = kt * 8 + tig;
        u32 ah0 = ah_[jr0 + ka], ah1 = ah_[jr1 + ka];
        u32 ah2 = ah_[jr0 + ka + 4], ah3 = ah_[jr1 + ka + 4];
        u32 al0 = al_[jr0 + ka], al1 = al_[jr1 + ka];
        u32 al2 = al_[jr0 + ka + 4], al3 = al_[jr1 + ka + 4];
#pragma unroll
        for (int n = 0; n < 8; n++) {
            int xb = ((nh * 8 + n) * 8 + gid) * 36 + ka;
            u32 bh0 = xh_[xb], bh1 = xh_[xb + 4];
            u32 bl0 = xl_[xb], bl1 = xl_[xb + 4];
            mma16(acc[n], ah0, ah1, ah2, ah3, bh0, bh1);
            mma16(acc[n], ah0, ah1, ah2, ah3, bl0, bl1);
            mma16(acc[n], al0, al1, al2, al3, bh0, bh1);
        }
    }

    float* gp = g_part + (size_t)blk * 20480;
    int jd0 = mt * 16 + gid;
#pragma unroll
    for (int n = 0; n < 8; n++) {
        int b = (nh * 8 + n) * 8 + 2 * tig;
        *(float2*)(gp + jd0 * 128 + b) =
            make_float2(acc[n][0] * scale, acc[n][1] * scale);
        *(float2*)(gp + (jd0 + 8) * 128 + b) =
            make_float2(acc[n][2] * scale, acc[n][3] * scale);
    }
}

// ---------------------------------------------------------------------------
// M-GEMM + delta: M[jd,rc] = sum_b V[jd,b]*X[rc,b];
// delta[r,j=mt] = sum_{d,c} W[jd,rc]*M[jd,rc]; warp = (mt, nh): 4 routes each
// ---------------------------------------------------------------------------
__device__ __forceinline__ void m_delta(char* smem, int t) {
    int lane = t & 31, w = t >> 5, gid = lane >> 2, tig = lane & 3;
    int mt = w % 10, nh = w / 10;
    const u32* v_  = (const u32*)(smem + O_V);
    const u32* bh_ = (const u32*)(smem + O_XTH);
    const u32* bl_ = (const u32*)(smem + O_XTL);
    int jr0 = (mt * 16 + gid) * 68, jr1 = (mt * 16 + gid + 8) * 68;

    float acc[4][4];
#pragma unroll
    for (int n = 0; n < 4; n++)
#pragma unroll
        for (int k = 0; k < 4; k++) acc[n][k] = 0.f;

#pragma unroll
    for (int kt = 0; kt < 8; kt++) {
        int ka = kt * 8 + tig;
        u32 a0 = v_[jr0 + ka], a1 = v_[jr1 + ka];
        u32 a2 = v_[jr0 + ka + 4], a3 = v_[jr1 + ka + 4];
#pragma unroll
        for (int n = 0; n < 4; n++) {
            int xb = ((nh * 4 + n) * 8 + gid) * 68 + ka;
            mma16(acc[n], a0, a1, a2, a3, bh_[xb], bh_[xb + 4]);
            mma16(acc[n], a0, a1, a2, a3, bl_[xb], bl_[xb + 4]);
        }
    }

    const u32* wh_ = (const u32*)(smem + O_WH);
    const u32* wl_ = (const u32*)(smem + O_WL);
    float* sD = (float*)(smem + O_SD);
    int jw0 = (mt * 16 + gid) * 36, jw1 = (mt * 16 + gid + 8) * 36;
#pragma unroll
    for (int n = 0; n < 4; n++) {
        int rr = nh * 4 + n;
        int wc = rr * 4 + tig;
        float2 wa = h2f2(wh_[jw0 + wc]), wb = h2f2(wl_[jw0 + wc]);
        float2 wc0 = make_float2(wa.x + wb.x, wa.y + wb.y);
        float2 wa1 = h2f2(wh_[jw1 + wc]), wb1 = h2f2(wl_[jw1 + wc]);
        float2 wc1 = make_float2(wa1.x + wb1.x, wa1.y + wb1.y);
        float dd = acc[n][0] * wc0.x + acc[n][1] * wc0.y
                 + acc[n][2] * wc1.x + acc[n][3] * wc1.y;
#pragma unroll
        for (int o = 16; o; o >>= 1)
            dd += __shfl_xor_sync(0xffffffffu, dd, o);
        if (lane == 0) sD[rr * 10 + mt] = dd;
    }
}

// ---------------------------------------------------------------------------
// merged reduce + squash: blocks 0..79 own (j, 16-b slice); 2-way k-split.
// ---------------------------------------------------------------------------
__device__ __forceinline__ void reduce_squash(char* smem, int blk, int t,
                                              float* out, int fin) {
    if (blk >= 80) return;
    int j = blk / 8, b0 = (blk % 8) * 16;
    float* SR  = (float*)(smem + O_SR);
    float* SQ  = (float*)(smem + O_SQ);
    float* SR2 = (float*)(smem + O_SR2);
    if (t < 512) {
        int item = t & 255, half = t >> 8;
        int d = item >> 4, bi = item & 15;
        const float* p = g_part + (size_t)half * 72 * 20480
                       + (j * 16 + d) * 128 + b0 + bi;
        float s0 = 0.f, s1 = 0.f, s2 = 0.f, s3 = 0.f;
#pragma unroll
        for (int k = 0; k < 72; k += 4) {
            s0 += __ldcg(p + (size_t)(k + 0) * 20480);
            s1 += __ldcg(p + (size_t)(k + 1) * 20480);
            s2 += __ldcg(p + (size_t)(k + 2) * 20480);
            s3 += __ldcg(p + (size_t)(k + 3) * 20480);
        }
        SR2[t] = (s0 + s1) + (s2 + s3);
    }
    __syncthreads();
    if (t < 256) SR[t] = SR2[t] + SR2[t + 256];
    __syncthreads();
    if (t < 16) {
        float sq = 0.f;
#pragma unroll
        for (int d = 0; d < 16; d++) { float z = SR[d * 16 + t]; sq += z * z; }
        SQ[t] = sqrtf(sq) / (1.f + sq);
    }
    __syncthreads();
    if (t < 256) {
        int d = t >> 4, bi = t & 15, b = b0 + bi;
        float v = SR[t] * SQ[bi];
        if (fin) out[b * 160 + j * 16 + d] = v;
        else g_vh[(j * 16 + d) * 128 + b] = __half_as_ushort(__float2half_rn(v));
    }
}

// ---------------------------------------------------------------------------
__device__ __forceinline__ void stage_v(char* smem, int t) {
    const u32* gv = (const u32*)g_vh;
    u32* sv = (u32*)(smem + O_V);
    for (int i = t; i < 10240; i += NT) {
        int jd = i >> 6, bu = i & 63;
        sv[jd * 68 + bu] = __ldcg(gv + i);
    }
    __syncthreads();
}

// softmax + W' rebuild (c∘W split to fp16 hi/lo)
__device__ __forceinline__ void route_update(char* smem, int t) {
    float* sB = (float*)(smem + O_SB);
    float* sD = (float*)(smem + O_SD);
    float* sC = (float*)(smem + O_SC);
    __syncthreads();                       // sD complete
    if (t < 80) sB[t] += sD[t] * (1.f / 128.f);
    __syncthreads();
    if (t < 80) {
        int r = t / 10;
        float m = -1e30f;
#pragma unroll
        for (int k = 0; k < 10; k++) m = fmaxf(m, sB[r * 10 + k]);
        float den = 0.f;
#pragma unroll
        for (int k = 0; k < 10; k++) den += expf(sB[r * 10 + k] - m);
        sC[t] = expf(sB[t] - m) / den;
    }
    __syncthreads();
    const u32* wh_ = (const u32*)(smem + O_WH);
    const u32* wl_ = (const u32*)(smem + O_WL);
    u32* ph_ = (u32*)(smem + O_PH);
    u32* pl_ = (u32*)(smem + O_PL);
    for (int i = t; i < 5120; i += NT) {   // uint pairs: jd x 32
        int jd = i >> 5, rcu = i & 31;
        float2 a = h2f2(wh_[jd * 36 + rcu]), b = h2f2(wl_[jd * 36 + rcu]);
        float c = sC[(rcu >> 2) * 10 + (jd >> 4)];
        float px = (a.x + b.x) * c, py = (a.y + b.y) * c;
        __half2 ph = __floats2half2_rn(px, py);
        float2 pf = __half22float2(ph);
        __half2 pl = __floats2half2_rn(px - pf.x, py - pf.y);
        ph_[jd * 36 + rcu] = *(u32*)&ph;
        pl_[jd * 36 + rcu] = *(u32*)&pl;
    }
    __syncthreads();
}

// ---------------------------------------------------------------------------
__global__ void __launch_bounds__(NT, 1)
caps_kernel(const float* __restrict__ x, const float* __restrict__ W,
            float* __restrict__ out) {
    extern __shared__ char smem[];
    int t = threadIdx.x, blk = blockIdx.x;

    // ---- load + fp16-split W chunk: [r][jd][c] -> halves [jd][rc] ----
    {
        __half* wh = (__half*)(smem + O_WH);
        __half* wl = (__half*)(smem + O_WL);
        const float* Wg = W + (size_t)blk * 8 * 1280;
        for (int i = t; i < 10240; i += NT) {
            int r = i / 1280, rem = i - r * 1280, jd = rem >> 3, c = rem & 7;
            float v = Wg[i];
            __half h = __float2half_rn(v);
            __half l = __float2half_rn(v - __half2float(h));
            wh[jd * 72 + r * 8 + c] = h;
            wl[jd * 72 + r * 8 + c] = l;
        }
    }
    // ---- load + split x chunk: halves [b][rc] and [rc][b] ----
    {
        __half* xh  = (__half*)(smem + O_XH);
        __half* xl  = (__half*)(smem + O_XL);
        __half* xth = (__half*)(smem + O_XTH);
        __half* xtl = (__half*)(smem + O_XTL);
        for (int i = t; i < 8192; i += NT) {
            int b = i >> 6, rc = i & 63;
            float v = x[(size_t)b * 9216 + blk * 64 + rc];
            __half h = __float2half_rn(v);
            __half l = __float2half_rn(v - __half2float(h));
            xh[b * 72 + rc] = h;   xl[b * 72 + rc] = l;
            xth[rc * 136 + b] = h; xtl[rc * 136 + b] = l;
        }
    }
    if (t < 80) ((float*)(smem + O_SB))[t] = 0.f;
    __syncthreads();

    // iter 1: c uniform 0.1 folded into store scale
    s_gemm(smem, t, blk, O_WH, O_WL, 0.1f);
    grid_sync(t);
    reduce_squash(smem, blk, t, out, 0);     // v1 -> g_vh
    grid_sync(t);

    // iter 2
    stage_v(smem, t);
    m_delta(smem, t);
    route_update(smem, t);                    // b1, c2, W'
    s_gemm(smem, t, blk, O_PH, O_PL, 1.f);
    grid_sync(t);
    reduce_squash(smem, blk, t, out, 0);     // v2 -> g_vh
    grid_sync(t);

    // iter 3
    stage_v(smem, t);
    m_delta(smem, t);
    route_update(smem, t);                    // b2, c3, W'
    s_gemm(smem, t, blk, O_PH, O_PL, 1.f);
    grid_sync(t);
    reduce_squash(smem, blk, t, out, 1);     // v3 -> out [B,10,16,1]
}

// ---------------------------------------------------------------------------
extern "C" void kernel_launch(void* const* d_in, const int* in_sizes, int n_in,
                              void* d_out, int out_size) {
    const float* x = (const float*)d_in[0];
    const float* W = (const float*)d_in[1];
    if (n_in >= 2 && in_sizes[0] == 1152 * 10 * 16 * 8) {  // inputs swapped
        x = (const float*)d_in[1];
        W = (const float*)d_in[0];
    }
    cudaFuncSetAttribute(caps_kernel,
                         cudaFuncAttributeMaxDynamicSharedMemorySize, SMEM_BYTES);
    caps_kernel<<<GRID, NT, SMEM_BYTES>>>(x, W, (float*)d_out);
}